// round 1
// baseline (speedup 1.0000x reference)
#include <cuda_runtime.h>
#include <math.h>

// Problem constants (fixed by the dataset)
#define SLEN   2048
#define DHEAD  64
#define NGROUP 32          // h*B = 8*4
#define MROWS  8192        // B*S
#define DMODEL 512

// Static scratch (allocation-free rule): ~576 MB total
__device__ float g_Q[(size_t)MROWS * DMODEL];
__device__ float g_K[(size_t)MROWS * DMODEL];
__device__ float g_V[(size_t)MROWS * DMODEL];
__device__ float g_O[(size_t)MROWS * DMODEL];
__device__ float g_S[(size_t)NGROUP * SLEN * SLEN];   // 512 MB scores/probs (in-place)

// ---------------------------------------------------------------------------
// Generic SGEMM: C[M,N] = A[M,K] @ B[K,N] + bias[N]
// 128x128 block tile, BK=8, 256 threads, 8x8 per-thread micro-tile.
// Requires M%128==0, N%128==0, K%8==0 (true for all our shapes).
// ---------------------------------------------------------------------------
__global__ __launch_bounds__(256) void sgemm_bias(
    const float* __restrict__ A, const float* __restrict__ B,
    const float* __restrict__ bias, float* __restrict__ C,
    int M, int N, int K)
{
    __shared__ float As[8][128];   // A tile stored transposed: As[k][m]
    __shared__ float Bs[8][128];   // Bs[k][n]

    const int tid = threadIdx.x;
    const int bx = blockIdx.x, by = blockIdx.y;
    const float* Ab = A + (size_t)by * 128 * K;
    const float* Bb = B + bx * 128;

    const int arow = tid >> 1, acol = (tid & 1) * 4;   // 128x8 A tile
    const int brow = tid >> 5, bcol = (tid & 31) * 4;  // 8x128 B tile
    const int ty = tid >> 4, tx = tid & 15;

    float acc[8][8] = {};

    for (int k0 = 0; k0 < K; k0 += 8) {
        float4 av = *(const float4*)(Ab + (size_t)arow * K + k0 + acol);
        As[acol + 0][arow] = av.x;
        As[acol + 1][arow] = av.y;
        As[acol + 2][arow] = av.z;
        As[acol + 3][arow] = av.w;
        *(float4*)&Bs[brow][bcol] =
            *(const float4*)(Bb + (size_t)(k0 + brow) * N + bcol);
        __syncthreads();

        #pragma unroll
        for (int k = 0; k < 8; k++) {
            float a[8], b[8];
            *(float4*)&a[0] = *(float4*)&As[k][ty * 8];
            *(float4*)&a[4] = *(float4*)&As[k][ty * 8 + 4];
            *(float4*)&b[0] = *(float4*)&Bs[k][tx * 8];
            *(float4*)&b[4] = *(float4*)&Bs[k][tx * 8 + 4];
            #pragma unroll
            for (int i = 0; i < 8; i++)
                #pragma unroll
                for (int j = 0; j < 8; j++)
                    acc[i][j] += a[i] * b[j];
        }
        __syncthreads();
    }

    #pragma unroll
    for (int i = 0; i < 8; i++) {
        int row = by * 128 + ty * 8 + i;
        float* Crow = C + (size_t)row * N + bx * 128;
        #pragma unroll
        for (int j = 0; j < 8; j += 4) {
            int col = tx * 8 + j;
            float4 bv = *(const float4*)(bias + bx * 128 + col);
            float4 o;
            o.x = acc[i][j + 0] + bv.x;
            o.y = acc[i][j + 1] + bv.y;
            o.z = acc[i][j + 2] + bv.z;
            o.w = acc[i][j + 3] + bv.w;
            *(float4*)(Crow + col) = o;
        }
    }
}

// ---------------------------------------------------------------------------
// Scores: for group g, S_g[2048,2048] = (Q_g @ K_g^T) * (1/sqrt(512))
// Q_g, K_g are [2048,64] row-major, contiguous slices of g_Q / g_K.
// 128x128 tile, K split into two 32-chunks. Tiles stored transposed [k][row].
// ---------------------------------------------------------------------------
__global__ __launch_bounds__(256) void scores_kernel(
    const float* __restrict__ Q, const float* __restrict__ K,
    float* __restrict__ S)
{
    __shared__ float Qs[32][132];
    __shared__ float Ks[32][132];

    const int tid = threadIdx.x;
    const int g = blockIdx.z;
    const float* Qg = Q + (size_t)g * SLEN * DHEAD + (size_t)blockIdx.y * 128 * DHEAD;
    const float* Kg = K + (size_t)g * SLEN * DHEAD + (size_t)blockIdx.x * 128 * DHEAD;
    const int ty = tid >> 4, tx = tid & 15;

    float acc[8][8] = {};

    for (int k0 = 0; k0 < DHEAD; k0 += 32) {
        #pragma unroll
        for (int l = 0; l < 4; l++) {
            int idx = tid + l * 256;
            int row = idx >> 3, c4 = (idx & 7) * 4;
            float4 qv = *(const float4*)(Qg + row * DHEAD + k0 + c4);
            Qs[c4 + 0][row] = qv.x; Qs[c4 + 1][row] = qv.y;
            Qs[c4 + 2][row] = qv.z; Qs[c4 + 3][row] = qv.w;
            float4 kv = *(const float4*)(Kg + row * DHEAD + k0 + c4);
            Ks[c4 + 0][row] = kv.x; Ks[c4 + 1][row] = kv.y;
            Ks[c4 + 2][row] = kv.z; Ks[c4 + 3][row] = kv.w;
        }
        __syncthreads();

        #pragma unroll
        for (int k = 0; k < 32; k++) {
            float a[8], b[8];
            *(float4*)&a[0] = *(float4*)&Qs[k][ty * 8];
            *(float4*)&a[4] = *(float4*)&Qs[k][ty * 8 + 4];
            *(float4*)&b[0] = *(float4*)&Ks[k][tx * 8];
            *(float4*)&b[4] = *(float4*)&Ks[k][tx * 8 + 4];
            #pragma unroll
            for (int i = 0; i < 8; i++)
                #pragma unroll
                for (int j = 0; j < 8; j++)
                    acc[i][j] += a[i] * b[j];
        }
        __syncthreads();
    }

    const float scale = 0.04419417382415922f;  // 1/sqrt(512)
    float* Sg = S + (size_t)g * SLEN * SLEN
                  + (size_t)blockIdx.y * 128 * SLEN + blockIdx.x * 128;
    #pragma unroll
    for (int i = 0; i < 8; i++) {
        float* Srow = Sg + (size_t)(ty * 8 + i) * SLEN;
        #pragma unroll
        for (int j = 0; j < 8; j += 4) {
            int col = tx * 8 + j;
            float4 o;
            o.x = acc[i][j + 0] * scale;
            o.y = acc[i][j + 1] * scale;
            o.z = acc[i][j + 2] * scale;
            o.w = acc[i][j + 3] * scale;
            *(float4*)(Srow + col) = o;
        }
    }
}

// ---------------------------------------------------------------------------
// Fused mean-threshold mask + softmax, in place, one block per row.
// keep = (s > mean(row)); p = softmax over kept entries, 0 elsewhere.
// ---------------------------------------------------------------------------
__global__ __launch_bounds__(256) void softmax_kernel(float* __restrict__ S)
{
    __shared__ float red[8];
    __shared__ float bc;

    float* p = S + (size_t)blockIdx.x * SLEN;
    const int tid = threadIdx.x;
    const int lane = tid & 31, warp = tid >> 5;

    float v[8];
    float s = 0.f;
    #pragma unroll
    for (int i = 0; i < 8; i++) { v[i] = p[tid + i * 256]; s += v[i]; }

    // block sum -> mean
    #pragma unroll
    for (int o = 16; o > 0; o >>= 1) s += __shfl_xor_sync(0xffffffffu, s, o);
    if (lane == 0) red[warp] = s;
    __syncthreads();
    if (tid == 0) {
        float t = 0.f;
        #pragma unroll
        for (int w = 0; w < 8; w++) t += red[w];
        bc = t;
    }
    __syncthreads();
    const float mean = bc * (1.0f / 2048.0f);

    // max over kept entries
    float m = -INFINITY;
    #pragma unroll
    for (int i = 0; i < 8; i++) if (v[i] > mean) m = fmaxf(m, v[i]);
    #pragma unroll
    for (int o = 16; o > 0; o >>= 1) m = fmaxf(m, __shfl_xor_sync(0xffffffffu, m, o));
    __syncthreads();
    if (lane == 0) red[warp] = m;
    __syncthreads();
    if (tid == 0) {
        float t = red[0];
        #pragma unroll
        for (int w = 1; w < 8; w++) t = fmaxf(t, red[w]);
        bc = t;
    }
    __syncthreads();
    const float M = bc;

    // exp sum over kept entries
    float z = 0.f;
    #pragma unroll
    for (int i = 0; i < 8; i++) {
        float e = (v[i] > mean) ? __expf(v[i] - M) : 0.f;
        v[i] = e;
        z += e;
    }
    #pragma unroll
    for (int o = 16; o > 0; o >>= 1) z += __shfl_xor_sync(0xffffffffu, z, o);
    __syncthreads();
    if (lane == 0) red[warp] = z;
    __syncthreads();
    if (tid == 0) {
        float t = 0.f;
        #pragma unroll
        for (int w = 0; w < 8; w++) t += red[w];
        bc = t;
    }
    __syncthreads();
    const float inv = 1.0f / bc;

    #pragma unroll
    for (int i = 0; i < 8; i++) p[tid + i * 256] = v[i] * inv;
}

// ---------------------------------------------------------------------------
// P @ V per group: O_g[2048,64] = P_g[2048,2048] @ V_g[2048,64]
// 128x64 tile, BK=32, 256 threads, 8x4 per-thread micro-tile.
// ---------------------------------------------------------------------------
__global__ __launch_bounds__(256) void pv_kernel(
    const float* __restrict__ P, const float* __restrict__ V,
    float* __restrict__ O)
{
    __shared__ float Ps[32][132];   // transposed: Ps[k][row]
    __shared__ float Vs[32][64];

    const int tid = threadIdx.x;
    const int g = blockIdx.z;
    const float* Pg = P + (size_t)g * SLEN * SLEN + (size_t)blockIdx.y * 128 * SLEN;
    const float* Vg = V + (size_t)g * SLEN * DHEAD;
    float* Og = O + (size_t)g * SLEN * DHEAD + (size_t)blockIdx.y * 128 * DHEAD;
    const int ty = tid >> 4, tx = tid & 15;

    float acc[8][4] = {};

    for (int k0 = 0; k0 < SLEN; k0 += 32) {
        #pragma unroll
        for (int l = 0; l < 4; l++) {
            int idx = tid + l * 256;
            int row = idx >> 3, c4 = (idx & 7) * 4;
            float4 pv = *(const float4*)(Pg + (size_t)row * SLEN + k0 + c4);
            Ps[c4 + 0][row] = pv.x; Ps[c4 + 1][row] = pv.y;
            Ps[c4 + 2][row] = pv.z; Ps[c4 + 3][row] = pv.w;
        }
        #pragma unroll
        for (int l = 0; l < 2; l++) {
            int idx = tid + l * 256;
            int row = idx >> 4, c4 = (idx & 15) * 4;
            *(float4*)&Vs[row][c4] =
                *(const float4*)(Vg + (size_t)(k0 + row) * DHEAD + c4);
        }
        __syncthreads();

        #pragma unroll
        for (int k = 0; k < 32; k++) {
            float a[8];
            *(float4*)&a[0] = *(float4*)&Ps[k][ty * 8];
            *(float4*)&a[4] = *(float4*)&Ps[k][ty * 8 + 4];
            float4 b = *(float4*)&Vs[k][tx * 4];
            #pragma unroll
            for (int i = 0; i < 8; i++) {
                acc[i][0] += a[i] * b.x;
                acc[i][1] += a[i] * b.y;
                acc[i][2] += a[i] * b.z;
                acc[i][3] += a[i] * b.w;
            }
        }
        __syncthreads();
    }

    #pragma unroll
    for (int i = 0; i < 8; i++) {
        float4 o;
        o.x = acc[i][0]; o.y = acc[i][1]; o.z = acc[i][2]; o.w = acc[i][3];
        *(float4*)(Og + (size_t)(ty * 8 + i) * DHEAD + tx * 4) = o;
    }
}

// ---------------------------------------------------------------------------
// Launch: x,y,Wq,bq,Wk,bk,Wv,bv,Wo,bo,n_heads
// ---------------------------------------------------------------------------
extern "C" void kernel_launch(void* const* d_in, const int* in_sizes, int n_in,
                              void* d_out, int out_size)
{
    const float* x  = (const float*)d_in[0];
    const float* y  = (const float*)d_in[1];
    const float* Wq = (const float*)d_in[2];
    const float* bq = (const float*)d_in[3];
    const float* Wk = (const float*)d_in[4];
    const float* bk = (const float*)d_in[5];
    const float* Wv = (const float*)d_in[6];
    const float* bv = (const float*)d_in[7];
    const float* Wo = (const float*)d_in[8];
    const float* bo = (const float*)d_in[9];
    float* out = (float*)d_out;

    float *Qp, *Kp, *Vp, *Op, *Sp;
    cudaGetSymbolAddress((void**)&Qp, g_Q);
    cudaGetSymbolAddress((void**)&Kp, g_K);
    cudaGetSymbolAddress((void**)&Vp, g_V);
    cudaGetSymbolAddress((void**)&Op, g_O);
    cudaGetSymbolAddress((void**)&Sp, g_S);

    dim3 gProj(DMODEL / 128, MROWS / 128);  // (4, 64)

    sgemm_bias<<<gProj, 256>>>(x, Wq, bq, Qp, MROWS, DMODEL, DMODEL);
    sgemm_bias<<<gProj, 256>>>(y, Wk, bk, Kp, MROWS, DMODEL, DMODEL);
    sgemm_bias<<<gProj, 256>>>(y, Wv, bv, Vp, MROWS, DMODEL, DMODEL);

    scores_kernel<<<dim3(16, 16, NGROUP), 256>>>(Qp, Kp, Sp);
    softmax_kernel<<<NGROUP * SLEN, 256>>>(Sp);
    pv_kernel<<<dim3(1, 16, NGROUP), 256>>>(Sp, Vp, Op);

    sgemm_bias<<<gProj, 256>>>(Op, Wo, bo, out, MROWS, DMODEL, DMODEL);
}

// round 2
// speedup vs baseline: 1.3893x; 1.3893x over previous
#include <cuda_runtime.h>
#include <math.h>
#include <stdint.h>

// Problem constants
#define SLEN   2048
#define DHEAD  64
#define NGROUP 32          // h*B = 8*4
#define MROWS  8192        // B*S
#define DMODEL 512
#define QK_SCALE 0.04419417382415922f   // 1/sqrt(512)

// Static scratch
__device__ float g_Q[(size_t)MROWS * DMODEL];
__device__ float g_K[(size_t)MROWS * DMODEL];
__device__ float g_V[(size_t)MROWS * DMODEL];
__device__ float g_O[(size_t)MROWS * DMODEL];
__device__ float g_Ksum[NGROUP * DHEAD];

// ---------------------------------------------------------------------------
// fp32 SGEMM with bias (proven in round 1) for the 4 projections.
// ---------------------------------------------------------------------------
__global__ __launch_bounds__(256) void sgemm_bias(
    const float* __restrict__ A, const float* __restrict__ B,
    const float* __restrict__ bias, float* __restrict__ C,
    int M, int N, int K)
{
    __shared__ float As[8][128];
    __shared__ float Bs[8][128];

    const int tid = threadIdx.x;
    const int bx = blockIdx.x, by = blockIdx.y;
    const float* Ab = A + (size_t)by * 128 * K;
    const float* Bb = B + bx * 128;

    const int arow = tid >> 1, acol = (tid & 1) * 4;
    const int brow = tid >> 5, bcol = (tid & 31) * 4;
    const int ty = tid >> 4, tx = tid & 15;

    float acc[8][8] = {};

    for (int k0 = 0; k0 < K; k0 += 8) {
        float4 av = *(const float4*)(Ab + (size_t)arow * K + k0 + acol);
        As[acol + 0][arow] = av.x;
        As[acol + 1][arow] = av.y;
        As[acol + 2][arow] = av.z;
        As[acol + 3][arow] = av.w;
        *(float4*)&Bs[brow][bcol] =
            *(const float4*)(Bb + (size_t)(k0 + brow) * N + bcol);
        __syncthreads();

        #pragma unroll
        for (int k = 0; k < 8; k++) {
            float a[8], b[8];
            *(float4*)&a[0] = *(float4*)&As[k][ty * 8];
            *(float4*)&a[4] = *(float4*)&As[k][ty * 8 + 4];
            *(float4*)&b[0] = *(float4*)&Bs[k][tx * 8];
            *(float4*)&b[4] = *(float4*)&Bs[k][tx * 8 + 4];
            #pragma unroll
            for (int i = 0; i < 8; i++)
                #pragma unroll
                for (int j = 0; j < 8; j++)
                    acc[i][j] += a[i] * b[j];
        }
        __syncthreads();
    }

    #pragma unroll
    for (int i = 0; i < 8; i++) {
        int row = by * 128 + ty * 8 + i;
        float* Crow = C + (size_t)row * N + bx * 128;
        #pragma unroll
        for (int j = 0; j < 8; j += 4) {
            int col = tx * 8 + j;
            float4 bv = *(const float4*)(bias + bx * 128 + col);
            float4 o;
            o.x = acc[i][j + 0] + bv.x;
            o.y = acc[i][j + 1] + bv.y;
            o.z = acc[i][j + 2] + bv.z;
            o.w = acc[i][j + 3] + bv.w;
            *(float4*)(Crow + col) = o;
        }
    }
}

// ---------------------------------------------------------------------------
// Per-group column sum of K:  Ksum[g][d] = sum_s K_g[s][d]
// ---------------------------------------------------------------------------
__global__ __launch_bounds__(256) void kcolsum_kernel(
    const float* __restrict__ K, float* __restrict__ Ksum)
{
    __shared__ float red[256];
    const int g = blockIdx.x;
    const float* Kg = K + (size_t)g * SLEN * DHEAD;
    const int c = threadIdx.x & 63;
    const int chunk = threadIdx.x >> 6;

    float s = 0.f;
    for (int r = chunk * 512; r < (chunk + 1) * 512; ++r)
        s += Kg[(size_t)r * DHEAD + c];
    red[threadIdx.x] = s;
    __syncthreads();
    if (threadIdx.x < 64)
        Ksum[g * DHEAD + threadIdx.x] =
            red[threadIdx.x] + red[64 + threadIdx.x] +
            red[128 + threadIdx.x] + red[192 + threadIdx.x];
}

// ---------------------------------------------------------------------------
// tf32 helpers
// ---------------------------------------------------------------------------
__device__ __forceinline__ uint32_t f32_to_tf32(float x) {
    uint32_t r;
    asm("cvt.rna.tf32.f32 %0, %1;" : "=r"(r) : "f"(x));
    return r;
}

__device__ __forceinline__ void mma_tf32(float (&c)[4],
    uint32_t a0, uint32_t a1, uint32_t a2, uint32_t a3,
    uint32_t b0, uint32_t b1)
{
    asm volatile(
        "mma.sync.aligned.m16n8k8.row.col.f32.tf32.tf32.f32 "
        "{%0,%1,%2,%3}, {%4,%5,%6,%7}, {%8,%9}, {%0,%1,%2,%3};\n"
        : "+f"(c[0]), "+f"(c[1]), "+f"(c[2]), "+f"(c[3])
        : "r"(a0), "r"(a1), "r"(a2), "r"(a3), "r"(b0), "r"(b1));
}

// ---------------------------------------------------------------------------
// Fused attention: per block = (group g, 128-query tile).
// Single pass over 16 key-tiles of 128:
//   S = (Q*scale) @ K^T  via 3xtf32 mma  (fp32-accurate)
//   mask: s > mean (mean = q·Ksum·scale/2048, computed up front)
//   p = exp(s) (no max subtraction needed; scores are small)
//   Z += rowsum(p);  O += p @ V (tf32 mma)
// Epilogue: O /= Z.
// smem: Qhi/Qlo[128][72], Ks[128][72], Vs[128][72], Ps[128][136] + misc
// ---------------------------------------------------------------------------
#define QP 72
#define PP 136
#define SMEM_FLOATS (9216*4 + 17408 + 64 + 128 + 128)

__global__ __launch_bounds__(256, 1) void fused_attn(
    const float* __restrict__ Q, const float* __restrict__ K,
    const float* __restrict__ V, const float* __restrict__ Ksum,
    float* __restrict__ O)
{
    extern __shared__ float sm[];
    float* Qhi   = sm;                  // [128][72]
    float* Qlo   = Qhi + 9216;
    float* Ks    = Qlo + 9216;          // [128][72]
    float* Vs    = Ks  + 9216;          // [128][72]
    float* Ps    = Vs  + 9216;          // [128][136]
    float* s_ksum = Ps + 17408;         // 64
    float* s_mean = s_ksum + 64;        // 128
    float* Zsm    = s_mean + 128;       // 128

    const int tid = threadIdx.x;
    const int lane = tid & 31, warp = tid >> 5;
    const int wm = warp >> 2, wn = warp & 3;     // warp grid 2x4
    const int lg = lane >> 2, la = lane & 3;
    const int g = blockIdx.y, qt = blockIdx.x;

    const float* Qg = Q + ((size_t)g * SLEN + qt * 128) * DHEAD;
    const float* Kg = K + (size_t)g * SLEN * DHEAD;
    const float* Vg = V + (size_t)g * SLEN * DHEAD;

    // --- load Q tile, pre-scale, split into tf32 hi/lo ---
    #pragma unroll
    for (int l = 0; l < 8; l++) {
        int idx = tid + l * 256;           // 2048 float4 slots
        int row = idx >> 4, c4 = (idx & 15) * 4;
        float4 v = *(const float4*)(Qg + row * DHEAD + c4);
        float vals[4] = {v.x, v.y, v.z, v.w};
        #pragma unroll
        for (int j = 0; j < 4; j++) {
            float x = vals[j] * QK_SCALE;
            uint32_t hi = f32_to_tf32(x);
            float hif = __uint_as_float(hi);
            Qhi[row * QP + c4 + j] = hif;
            Qlo[row * QP + c4 + j] = __uint_as_float(f32_to_tf32(x - hif));
        }
    }
    if (tid < 64)  s_ksum[tid] = Ksum[g * DHEAD + tid];
    if (tid < 128) Zsm[tid] = 0.f;
    __syncthreads();

    // --- per-row mean threshold (scaled consistently with scores) ---
    if (tid < 128) {
        float acc = 0.f;
        #pragma unroll
        for (int d = 0; d < 64; d++)
            acc += (Qhi[tid * QP + d] + Qlo[tid * QP + d]) * s_ksum[d];
        s_mean[tid] = acc * (1.0f / 2048.0f);
    }
    __syncthreads();

    float oacc[4][2][4];
    float Zreg[4][2];
    #pragma unroll
    for (int mf = 0; mf < 4; mf++) {
        Zreg[mf][0] = Zreg[mf][1] = 0.f;
        #pragma unroll
        for (int nf = 0; nf < 2; nf++)
            #pragma unroll
            for (int j = 0; j < 4; j++) oacc[mf][nf][j] = 0.f;
    }

    for (int kt = 0; kt < 16; ++kt) {
        // --- load K,V tile [128][64] ---
        #pragma unroll
        for (int l = 0; l < 8; l++) {
            int idx = tid + l * 256;
            int row = idx >> 4, c4 = (idx & 15) * 4;
            size_t goff = ((size_t)(kt * 128 + row)) * DHEAD + c4;
            *(float4*)(Ks + row * QP + c4) = *(const float4*)(Kg + goff);
            *(float4*)(Vs + row * QP + c4) = *(const float4*)(Vg + goff);
        }
        __syncthreads();

        // === S = Q@K^T, 3xtf32 ===
        float sacc[4][4][4];
        #pragma unroll
        for (int mf = 0; mf < 4; mf++)
            #pragma unroll
            for (int nf = 0; nf < 4; nf++)
                #pragma unroll
                for (int j = 0; j < 4; j++) sacc[mf][nf][j] = 0.f;

        #pragma unroll
        for (int kk = 0; kk < 8; ++kk) {
            uint32_t ahi[4][4], alo[4][4];
            #pragma unroll
            for (int mf = 0; mf < 4; mf++) {
                int r0 = wm * 64 + mf * 16 + lg;
                int c0 = kk * 8 + la;
                ahi[mf][0] = __float_as_uint(Qhi[r0 * QP + c0]);
                ahi[mf][1] = __float_as_uint(Qhi[(r0 + 8) * QP + c0]);
                ahi[mf][2] = __float_as_uint(Qhi[r0 * QP + c0 + 4]);
                ahi[mf][3] = __float_as_uint(Qhi[(r0 + 8) * QP + c0 + 4]);
                alo[mf][0] = __float_as_uint(Qlo[r0 * QP + c0]);
                alo[mf][1] = __float_as_uint(Qlo[(r0 + 8) * QP + c0]);
                alo[mf][2] = __float_as_uint(Qlo[r0 * QP + c0 + 4]);
                alo[mf][3] = __float_as_uint(Qlo[(r0 + 8) * QP + c0 + 4]);
            }
            #pragma unroll
            for (int nf = 0; nf < 4; nf++) {
                int kr = wn * 32 + nf * 8 + lg;
                int kc = kk * 8 + la;
                float b0f = Ks[kr * QP + kc];
                float b1f = Ks[kr * QP + kc + 4];
                uint32_t bhi0 = f32_to_tf32(b0f);
                uint32_t bhi1 = f32_to_tf32(b1f);
                uint32_t blo0 = f32_to_tf32(b0f - __uint_as_float(bhi0));
                uint32_t blo1 = f32_to_tf32(b1f - __uint_as_float(bhi1));
                #pragma unroll
                for (int mf = 0; mf < 4; mf++) {
                    mma_tf32(sacc[mf][nf], ahi[mf][0], ahi[mf][1], ahi[mf][2], ahi[mf][3], bhi0, bhi1);
                    mma_tf32(sacc[mf][nf], alo[mf][0], alo[mf][1], alo[mf][2], alo[mf][3], bhi0, bhi1);
                    mma_tf32(sacc[mf][nf], ahi[mf][0], ahi[mf][1], ahi[mf][2], ahi[mf][3], blo0, blo1);
                }
            }
        }

        // === mask + exp + store P ===
        #pragma unroll
        for (int mf = 0; mf < 4; mf++) {
            int r0 = wm * 64 + mf * 16 + lg;
            float m0 = s_mean[r0], m1 = s_mean[r0 + 8];
            #pragma unroll
            for (int nf = 0; nf < 4; nf++) {
                int col = wn * 32 + nf * 8 + 2 * la;
                float s0 = sacc[mf][nf][0], s1 = sacc[mf][nf][1];
                float s2 = sacc[mf][nf][2], s3 = sacc[mf][nf][3];
                float p0 = (s0 > m0) ? __expf(s0) : 0.f;
                float p1 = (s1 > m0) ? __expf(s1) : 0.f;
                float p2 = (s2 > m1) ? __expf(s2) : 0.f;
                float p3 = (s3 > m1) ? __expf(s3) : 0.f;
                Zreg[mf][0] += p0 + p1;
                Zreg[mf][1] += p2 + p3;
                *(float2*)(Ps + r0 * PP + col)       = make_float2(p0, p1);
                *(float2*)(Ps + (r0 + 8) * PP + col) = make_float2(p2, p3);
            }
        }
        __syncthreads();

        // === O += P @ V, tf32 ===
        #pragma unroll
        for (int kk = 0; kk < 16; ++kk) {
            uint32_t bv[2][2];
            #pragma unroll
            for (int nf = 0; nf < 2; nf++) {
                int vc = wn * 16 + nf * 8 + lg;
                int vr = kk * 8 + la;
                bv[nf][0] = f32_to_tf32(Vs[vr * QP + vc]);
                bv[nf][1] = f32_to_tf32(Vs[(vr + 4) * QP + vc]);
            }
            #pragma unroll
            for (int mf = 0; mf < 4; mf++) {
                int r0 = wm * 64 + mf * 16 + lg;
                int c0 = kk * 8 + la;
                uint32_t a0 = f32_to_tf32(Ps[r0 * PP + c0]);
                uint32_t a1 = f32_to_tf32(Ps[(r0 + 8) * PP + c0]);
                uint32_t a2 = f32_to_tf32(Ps[r0 * PP + c0 + 4]);
                uint32_t a3 = f32_to_tf32(Ps[(r0 + 8) * PP + c0 + 4]);
                mma_tf32(oacc[mf][0], a0, a1, a2, a3, bv[0][0], bv[0][1]);
                mma_tf32(oacc[mf][1], a0, a1, a2, a3, bv[1][0], bv[1][1]);
            }
        }
        __syncthreads();
    }

    // --- Z reduction across lanes & warps ---
    #pragma unroll
    for (int mf = 0; mf < 4; mf++)
        #pragma unroll
        for (int h = 0; h < 2; h++) {
            float z = Zreg[mf][h];
            z += __shfl_xor_sync(0xffffffffu, z, 1);
            z += __shfl_xor_sync(0xffffffffu, z, 2);
            if (la == 0)
                atomicAdd(&Zsm[wm * 64 + mf * 16 + h * 8 + lg], z);
        }
    __syncthreads();

    // --- normalize and write O ---
    float* Og = O + ((size_t)g * SLEN + qt * 128) * DHEAD;
    #pragma unroll
    for (int mf = 0; mf < 4; mf++) {
        int r0 = wm * 64 + mf * 16 + lg;
        float iz0 = 1.f / Zsm[r0];
        float iz1 = 1.f / Zsm[r0 + 8];
        #pragma unroll
        for (int nf = 0; nf < 2; nf++) {
            int col = wn * 16 + nf * 8 + 2 * la;
            *(float2*)(Og + (size_t)r0 * DHEAD + col) =
                make_float2(oacc[mf][nf][0] * iz0, oacc[mf][nf][1] * iz0);
            *(float2*)(Og + (size_t)(r0 + 8) * DHEAD + col) =
                make_float2(oacc[mf][nf][2] * iz1, oacc[mf][nf][3] * iz1);
        }
    }
}

// ---------------------------------------------------------------------------
// Launch
// ---------------------------------------------------------------------------
extern "C" void kernel_launch(void* const* d_in, const int* in_sizes, int n_in,
                              void* d_out, int out_size)
{
    const float* x  = (const float*)d_in[0];
    const float* y  = (const float*)d_in[1];
    const float* Wq = (const float*)d_in[2];
    const float* bq = (const float*)d_in[3];
    const float* Wk = (const float*)d_in[4];
    const float* bk = (const float*)d_in[5];
    const float* Wv = (const float*)d_in[6];
    const float* bv = (const float*)d_in[7];
    const float* Wo = (const float*)d_in[8];
    const float* bo = (const float*)d_in[9];
    float* out = (float*)d_out;

    float *Qp, *Kp, *Vp, *Op, *KsumP;
    cudaGetSymbolAddress((void**)&Qp, g_Q);
    cudaGetSymbolAddress((void**)&Kp, g_K);
    cudaGetSymbolAddress((void**)&Vp, g_V);
    cudaGetSymbolAddress((void**)&Op, g_O);
    cudaGetSymbolAddress((void**)&KsumP, g_Ksum);

    const int smem_bytes = SMEM_FLOATS * 4;
    cudaFuncSetAttribute(fused_attn, cudaFuncAttributeMaxDynamicSharedMemorySize,
                         smem_bytes);

    dim3 gProj(DMODEL / 128, MROWS / 128);  // (4, 64)

    sgemm_bias<<<gProj, 256>>>(x, Wq, bq, Qp, MROWS, DMODEL, DMODEL);
    sgemm_bias<<<gProj, 256>>>(y, Wk, bk, Kp, MROWS, DMODEL, DMODEL);
    sgemm_bias<<<gProj, 256>>>(y, Wv, bv, Vp, MROWS, DMODEL, DMODEL);

    kcolsum_kernel<<<NGROUP, 256>>>(Kp, KsumP);

    fused_attn<<<dim3(16, NGROUP), 256, smem_bytes>>>(Qp, Kp, Vp, KsumP, Op);

    sgemm_bias<<<gProj, 256>>>(Op, Wo, bo, out, MROWS, DMODEL, DMODEL);
}